// round 9
// baseline (speedup 1.0000x reference)
#include <cuda_runtime.h>

// MaskedLoss: loss = sum_b sum_{unique (r,c)} (y_true[b,r,c] - y_pred[b,r,c])^2
// B=64, N=1000, K=128. Sparse gather (~8K of 64M positions).
// 64 blocks x 32 threads (ONE warp per block, 4 pairs per thread):
//   - no __syncthreads anywhere; width verdict is warp-local (ballot)
//   - two serial memory epochs: [index uint4 load] -> [8-wide gather]
//   - dedup hash CAS hidden under gather latency
//   - ONE packed u64 atomic per block (64 chip-wide arrivals): pre-value is
//     simultaneously ticket and running total.

#define MB_B   64
#define MB_N   1000
#define MB_ARRIVALS 64

// Packed accumulator: bits [56,64) = arrival count, bits [0,56) = fixed-point
// sum (scale 2^30; |sum| < 2^20 so no carry into count). Zero at module load;
// last block resets it -> identical state on every graph replay.
__device__ unsigned long long g_pack;

__global__ __launch_bounds__(32)
void masked_loss_fused_kernel(const float* __restrict__ y_true,
                              const float* __restrict__ y_pred,
                              const unsigned int* __restrict__ rows_w,
                              const unsigned int* __restrict__ cols_w,
                              float* __restrict__ out)
{
    const int t = threadIdx.x;   // 0..31
    const int b = blockIdx.x;    // 0..63 : batch row

    __shared__ int s_tab[256];   // dedup hash table
    #pragma unroll
    for (int i = 0; i < 8; ++i) s_tab[t + 32 * i] = -1;

    // ---- epoch 1 (T0): one uint4 per thread per array = first 512B of each.
    // int32: q0 lanes are words 4t..4t+3  -> exactly pairs 4t..4t+3.
    // int64: q0 = elements 2t (lo=x,hi=y) and 2t+1 (lo=z,hi=w).
    const uint4 r0 = ((const uint4*)rows_w)[t];
    const uint4 c0 = ((const uint4*)cols_w)[t];

    // Non-faulting L2 prefetch of bytes [512,1024) (int64 upper half),
    // concurrent with epoch 1. Hint only — safe for either width.
    if (t < 4) {
        asm volatile("prefetch.global.L2 [%0];"
                     :: "l"((const char*)rows_w + 512 + t * 128));
    } else if (t < 8) {
        asm volatile("prefetch.global.L2 [%0];"
                     :: "l"((const char*)cols_w + 512 + (t - 4) * 128));
    }

    // ---- width verdict, warp-local (no barrier, no shared flag).
    // int64 (values<1000): hi-words y,w are 0 for all 64 sampled elements.
    // int32: y,w are random indices in [0,1000); all-zero prob ~1e-192.
    const bool is_i32 =
        (__ballot_sync(0xffffffffu, (r0.y | r0.w) != 0u) != 0u);

    int rr[4], cc[4];
    if (is_i32) {
        rr[0] = (int)r0.x; rr[1] = (int)r0.y; rr[2] = (int)r0.z; rr[3] = (int)r0.w;
        cc[0] = (int)c0.x; cc[1] = (int)c0.y; cc[2] = (int)c0.z; cc[3] = (int)c0.w;
    } else {
        // elements 64+2t, 64+2t+1 live in bytes [512,1024) — in-bounds for
        // int64 (buffer is 1024B) and L2-prefetched above (~L2-hit latency).
        const uint4 r1 = ((const uint4*)rows_w)[t + 32];
        const uint4 c1 = ((const uint4*)cols_w)[t + 32];
        rr[0] = (int)r0.x; rr[1] = (int)r0.z; rr[2] = (int)r1.x; rr[3] = (int)r1.z;
        cc[0] = (int)c0.x; cc[1] = (int)c0.z; cc[2] = (int)c1.x; cc[3] = (int)c1.z;
    }

    // ---- epoch 2: issue all 8 gathers immediately (independent of dedup;
    //      duplicates hit the same address — L2 dedups). Offsets < 2^31.
    int   idx[4];
    float yt[4], yp[4];
    #pragma unroll
    for (int i = 0; i < 4; ++i) {
        idx[i] = rr[i] * MB_N + cc[i];
        const int off = b * (MB_N * MB_N) + idx[i];
        yt[i] = __ldg(y_true + off);
        yp[i] = __ldg(y_pred + off);
    }

    __syncwarp();   // s_tab init visible to all lanes before CAS

    // ---- dedup via shared-mem hash, hidden under gather latency.
    //      Any single winner per value is correct.
    bool uniq[4];
    #pragma unroll
    for (int i = 0; i < 4; ++i) {
        unsigned int h = ((unsigned int)idx[i] * 2654435761u) >> 24;  // 0..255
        uniq[i] = false;
        for (;;) {
            int prev = atomicCAS(&s_tab[h], -1, idx[i]);
            if (prev == -1) { uniq[i] = true; break; }
            if (prev == idx[i]) break;
            h = (h + 1) & 255;
        }
    }

    float v = 0.0f;
    #pragma unroll
    for (int i = 0; i < 4; ++i) {
        const float d = yt[i] - yp[i];
        if (uniq[i]) v = fmaf(d, d, v);
    }

    // ---- warp reduce = block reduce (single warp) -------------------------
    #pragma unroll
    for (int o = 16; o > 0; o >>= 1)
        v += __shfl_down_sync(0xffffffffu, v, o);

    // ---- tail: ONE packed atomic per block (64 arrivals chip-wide) --------
    if (t == 0) {
        const unsigned long long contrib =
            (1ULL << 56) |
            (unsigned long long)__float2ll_rn(v * 1073741824.0f);  // * 2^30
        const unsigned long long pre = atomicAdd(&g_pack, contrib);

        if ((pre >> 56) == (unsigned long long)(MB_ARRIVALS - 1)) {
            // 64th arrival: pre already carries the other 63 block sums.
            const long long fixed =
                (long long)((pre + contrib) & 0x00FFFFFFFFFFFFFFULL);
            out[0] = (float)((double)fixed * (1.0 / 1073741824.0));
            g_pack = 0ULL;   // reset for the next graph replay (sole writer;
                             // stream order publishes before the next launch)
        }
    }
}

// ---------------------------------------------------------------------------
// Launch contract
//   d_in[0] = y_true  (float32, B*N*N)
//   d_in[1] = y_pred  (float32, B*N*N)
//   d_in[2] = rows    (int64 or int32, K)
//   d_in[3] = cols    (int64 or int32, K)
//   d_out   = float32 scalar
// ---------------------------------------------------------------------------
extern "C" void kernel_launch(void* const* d_in, const int* in_sizes, int n_in,
                              void* d_out, int out_size)
{
    const float*        y_true = (const float*)d_in[0];
    const float*        y_pred = (const float*)d_in[1];
    const unsigned int* rows_w = (const unsigned int*)d_in[2];
    const unsigned int* cols_w = (const unsigned int*)d_in[3];
    float*              out    = (float*)d_out;

    masked_loss_fused_kernel<<<MB_B, 32>>>(y_true, y_pred, rows_w, cols_w, out);
}

// round 10
// speedup vs baseline: 1.0731x; 1.0731x over previous
#include <cuda_runtime.h>

// MaskedLoss: loss = sum_b sum_{unique (r,c)} (y_true[b,r,c] - y_pred[b,r,c])^2
// B=64, N=1000, K=128. Sparse gather (~8K of 64M positions).
// 64 blocks x 128 threads (4 warps). Critical path:
//   [uint2 index load] -> (warp-local width ballot) -> [gather] -> reduce
// with the dedup hash CAS hidden under gather latency. Tail is hierarchical
// packed-ticket atomics: 4 warp leaders -> 1 smem u64 atomic; 4th arrival ->
// 1 global u64 atomic (64 chip-wide same-address ops instead of 256); the
// 64th global arrival's pre-value IS the total (ticket == data, no fences).

#define MB_B   64
#define MB_N   1000

// Packed global accumulator: bits [56,64) = block-arrival count, bits [0,56)
// = fixed-point sum (scale 2^30; total < 2^50, no carry into count).
// Zero at module load; last arrival resets it -> identical state per replay.
__device__ unsigned long long g_pack;

__global__ __launch_bounds__(128)
void masked_loss_fused_kernel(const float* __restrict__ y_true,
                              const float* __restrict__ y_pred,
                              const unsigned int* __restrict__ rows_w,
                              const unsigned int* __restrict__ cols_w,
                              float* __restrict__ out)
{
    const int t = threadIdx.x;   // 0..127
    const int b = blockIdx.x;    // 0..63 : batch row

    __shared__ int                s_tab[256];  // dedup hash table
    __shared__ unsigned long long s_pack;      // block packed [cnt:8|sum:56]

    s_tab[t]       = -1;
    s_tab[t + 128] = -1;
    if (t == 0) s_pack = 0ULL;

    // ---- epoch 1 (T0): every thread loads uint2 at (t & 63) — the first
    // 512B of each index array. Warps 2,3 re-read the same lines (coalesced
    // broadcast). int64: pair = element (t&63) (lo=x, hi=y). int32: pair =
    // words 2(t&63), 2(t&63)+1 = indices 2(t&63) and 2(t&63)+1.
    const int p = t & 63;
    uint2 r2 = ((const uint2*)rows_w)[p];
    uint2 c2 = ((const uint2*)cols_w)[p];

    // Non-faulting L2 prefetch of bytes [512,1024) (int64 upper half),
    // issued by warps 2,3 concurrently with epoch 1. Safe for either width.
    if (t >= 64 && t < 68) {
        asm volatile("prefetch.global.L2 [%0];"
                     :: "l"((const char*)rows_w + 512 + (t - 64) * 128));
    } else if (t >= 96 && t < 100) {
        asm volatile("prefetch.global.L2 [%0];"
                     :: "l"((const char*)cols_w + 512 + (t - 96) * 128));
    }

    // Barrier covers only the s_tab/s_pack stores above — it does NOT wait
    // on any load result (the width verdict below is warp-local).
    __syncthreads();

    // ---- width verdict, per-warp (no shared flag). Each warp sampled 32
    // hi-words from the first 512B. int64 (values<1000): all zero. int32:
    // 32 random indices in [0,1000); all-zero probability ~1e-96.
    const bool is_i32 = (__ballot_sync(0xffffffffu, r2.y != 0u) != 0u);

    int r, c;
    if (is_i32) {
        // thread t<64 -> even index 2p (.x); t>=64 -> odd index 2p+1 (.y)
        r = (t < 64) ? (int)r2.x : (int)r2.y;
        c = (t < 64) ? (int)c2.x : (int)c2.y;
    } else {
        // element t; threads >=64 reload from bytes [512,1024) — in-bounds
        // for int64 (buffer is 1024B) and L2-prefetched above (~L2 hit).
        if (t >= 64) {
            r2 = ((const uint2*)rows_w)[t];
            c2 = ((const uint2*)cols_w)[t];
        }
        r = (int)r2.x;
        c = (int)c2.x;
    }
    const int my = r * MB_N + c;

    // ---- epoch 2: issue gathers immediately (independent of dedup; duplicate
    // threads hit the same address — L2 dedups). Offset < 2^31.
    const int off = b * (MB_N * MB_N) + my;
    const float yt = __ldg(y_true + off);
    const float yp = __ldg(y_pred + off);

    // ---- dedup via shared-mem hash, hidden under gather latency.
    // Any single winner per value is correct (duplicates address the same
    // element).
    unsigned int h = ((unsigned int)my * 2654435761u) >> 24;  // 0..255
    bool uniq = false;
    for (;;) {
        int prev = atomicCAS(&s_tab[h], -1, my);
        if (prev == -1) { uniq = true; break; }
        if (prev == my) break;
        h = (h + 1) & 255;
    }

    const float d = yt - yp;
    float v = uniq ? d * d : 0.0f;

    // ---- warp reduce -------------------------------------------------------
    #pragma unroll
    for (int o = 16; o > 0; o >>= 1)
        v += __shfl_down_sync(0xffffffffu, v, o);

    // ---- hierarchical packed-ticket tail -----------------------------------
    if ((t & 31) == 0) {
        // level 1: 4 warp leaders -> one smem u64 atomic (no barrier needed;
        // the pre-value count tells the 4th arrival it holds the block total).
        const unsigned long long contrib =
            (1ULL << 56) |
            (unsigned long long)__float2ll_rn(v * 1073741824.0f);  // * 2^30
        const unsigned long long pre_s = atomicAdd(&s_pack, contrib);

        if ((pre_s >> 56) == 3ULL) {   // 4th warp of this block
            const unsigned long long blk =
                (pre_s + contrib) & 0x00FFFFFFFFFFFFFFULL;  // block fixed sum

            // level 2: one global u64 atomic per block (64 chip-wide).
            const unsigned long long gcontrib = (1ULL << 56) | blk;
            const unsigned long long pre_g = atomicAdd(&g_pack, gcontrib);

            if ((pre_g >> 56) == (unsigned long long)(MB_B - 1)) {
                // 64th block: pre_g already carries the other 63 sums.
                const long long fixed =
                    (long long)((pre_g + gcontrib) & 0x00FFFFFFFFFFFFFFULL);
                out[0] = (float)((double)fixed * (1.0 / 1073741824.0));
                g_pack = 0ULL;   // reset for the next graph replay (sole
                                 // writer; stream order publishes it)
            }
        }
    }
}

// ---------------------------------------------------------------------------
// Launch contract
//   d_in[0] = y_true  (float32, B*N*N)
//   d_in[1] = y_pred  (float32, B*N*N)
//   d_in[2] = rows    (int64 or int32, K)
//   d_in[3] = cols    (int64 or int32, K)
//   d_out   = float32 scalar
// ---------------------------------------------------------------------------
extern "C" void kernel_launch(void* const* d_in, const int* in_sizes, int n_in,
                              void* d_out, int out_size)
{
    const float*        y_true = (const float*)d_in[0];
    const float*        y_pred = (const float*)d_in[1];
    const unsigned int* rows_w = (const unsigned int*)d_in[2];
    const unsigned int* cols_w = (const unsigned int*)d_in[3];
    float*              out    = (float*)d_out;

    masked_loss_fused_kernel<<<MB_B, 128>>>(y_true, y_pred, rows_w, cols_w, out);
}

// round 12
// speedup vs baseline: 1.3413x; 1.2500x over previous
#include <cuda_runtime.h>

// MaskedLoss: loss = sum_b sum_{unique (r,c)} (y_true[b,r,c] - y_pred[b,r,c])^2
// B=64, N=1000, K=128. Sparse gather (~8K of 64M positions).
// 64 blocks x 128 threads (4 warps). Critical path:
//   [uint2 index load] -> warp-local width ballot -> [gather] ->
//   F2I + redux.sync.add.s32 -> packed smem atomic -> packed global atomic.
// Dedup hash CAS hidden under gather latency. Everything is fixed-point
// (scale 2^22) from the warp reduce onward; ticket == data: the 64th global
// arrival's pre-value IS the total — no fences, no second round trip.

#define MB_B     64
#define MB_N     1000
#define MB_SCALE 4194304.0f          // 2^22
#define MB_INV   (1.0f / 4194304.0f)

// Packed global accumulator: bits [56,64) = block-arrival count, bits [0,56)
// = fixed-point sum (scale 2^22; total < 2^37, no carry into count).
// Zero at module load; last arrival resets it -> identical state per replay.
__device__ unsigned long long g_pack;

// Single-instruction integer warp sum (sm_80+; f32 redux doesn't exist on sm_103).
__device__ __forceinline__ int warp_sum_s32(int v) {
    int r;
    asm volatile("redux.sync.add.s32 %0, %1, 0xffffffff;" : "=r"(r) : "r"(v));
    return r;
}

__global__ __launch_bounds__(128)
void masked_loss_fused_kernel(const float* __restrict__ y_true,
                              const float* __restrict__ y_pred,
                              const unsigned int* __restrict__ rows_w,
                              const unsigned int* __restrict__ cols_w,
                              float* __restrict__ out)
{
    const int t = threadIdx.x;   // 0..127
    const int b = blockIdx.x;    // 0..63 : batch row

    __shared__ int                s_tab[256];  // dedup hash table
    __shared__ unsigned long long s_pack;      // block packed [cnt:8|sum:56]

    s_tab[t]       = -1;
    s_tab[t + 128] = -1;
    if (t == 0) s_pack = 0ULL;

    // ---- epoch 1 (T0): every thread loads uint2 at (t & 63) — the first
    // 512B of each index array (warps 2,3 re-read the same lines, coalesced
    // broadcast). int64: the pair IS element (t&63) (lo=x, hi=y). int32:
    // pair = indices 2(t&63), 2(t&63)+1.
    const int p = t & 63;
    uint2 r2 = __ldg((const uint2*)rows_w + p);
    uint2 c2 = __ldg((const uint2*)cols_w + p);

    // Non-faulting L2 prefetch of bytes [512,1024) (int64 upper half),
    // issued by warps 2,3 concurrently with epoch 1. Safe for either width.
    if (t >= 64 && t < 68) {
        asm volatile("prefetch.global.L2 [%0];"
                     :: "l"((const char*)rows_w + 512 + (t - 64) * 128));
    } else if (t >= 96 && t < 100) {
        asm volatile("prefetch.global.L2 [%0];"
                     :: "l"((const char*)cols_w + 512 + (t - 96) * 128));
    }

    // Barrier covers only the s_tab/s_pack stores above — it does NOT wait
    // on any load result (the width verdict below is warp-local).
    __syncthreads();

    // ---- width verdict, per-warp (no shared flag). Each warp sampled 32
    // hi-words from the first 512B. int64 (values<1000): all zero. int32:
    // 32 random indices in [0,1000); all-zero probability ~1e-96.
    const bool is_i32 = (__ballot_sync(0xffffffffu, r2.y != 0u) != 0u);

    int r, c;
    if (is_i32) {
        // thread t<64 -> even index 2p (.x); t>=64 -> odd index 2p+1 (.y)
        r = (t < 64) ? (int)r2.x : (int)r2.y;
        c = (t < 64) ? (int)c2.x : (int)c2.y;
    } else {
        // element t; threads >=64 reload from bytes [512,1024) — in-bounds
        // for int64 (buffer is 1024B) and L2-prefetched above (~L2 hit).
        if (t >= 64) {
            r2 = __ldg((const uint2*)rows_w + t);
            c2 = __ldg((const uint2*)cols_w + t);
        }
        r = (int)r2.x;
        c = (int)c2.x;
    }
    const int my = r * MB_N + c;

    // ---- epoch 2: issue gathers immediately (independent of dedup; duplicate
    // threads hit the same address — L2 dedups). Offset < 2^31.
    const int off = b * (MB_N * MB_N) + my;
    const float yt = __ldg(y_true + off);
    const float yp = __ldg(y_pred + off);

    // ---- dedup via shared-mem hash, hidden under gather latency.
    // Any single winner per value is correct (duplicates address the same
    // element).
    unsigned int h = ((unsigned int)my * 2654435761u) >> 24;  // 0..255
    bool uniq = false;
    for (;;) {
        int prev = atomicCAS(&s_tab[h], -1, my);
        if (prev == -1) { uniq = true; break; }
        if (prev == my) break;
        h = (h + 1) & 255;
    }

    const float d = yt - yp;
    // Fixed-point (2^22) BEFORE the reduce so the warp sum is one REDUX.S32.
    // Per-thread d^2 <~ 50 -> <2^30; warp sum <~ 2^31 headroom holds.
    const int vq = uniq ? __float2int_rn(d * d * MB_SCALE) : 0;

    // ---- warp reduce: one REDUX instead of 5 dependent SHFLs ---------------
    const int wsum = warp_sum_s32(vq);

    // ---- hierarchical packed-ticket tail -----------------------------------
    if ((t & 31) == 0) {
        // level 1: 4 warp leaders -> one smem u64 atomic; the pre-value count
        // tells the 4th arrival it holds the block total (no barrier).
        const unsigned long long contrib =
            (1ULL << 56) | (unsigned long long)(long long)wsum;
        const unsigned long long pre_s = atomicAdd(&s_pack, contrib);

        if ((pre_s >> 56) == 3ULL) {   // 4th warp of this block
            const unsigned long long blk =
                (pre_s + contrib) & 0x00FFFFFFFFFFFFFFULL;  // block fixed sum

            // level 2: one global u64 atomic per block (64 chip-wide).
            const unsigned long long gcontrib = (1ULL << 56) | blk;
            const unsigned long long pre_g = atomicAdd(&g_pack, gcontrib);

            if ((pre_g >> 56) == (unsigned long long)(MB_B - 1)) {
                // 64th block: pre_g already carries the other 63 sums.
                const long long fixed =
                    (long long)((pre_g + gcontrib) & 0x00FFFFFFFFFFFFFFULL);
                // s64 -> f32 rounds once; * 2^-22 is exact (power of two).
                out[0] = (float)fixed * MB_INV;
                g_pack = 0ULL;   // reset for the next graph replay (sole
                                 // writer; stream order publishes it)
            }
        }
    }
}

// ---------------------------------------------------------------------------
// Launch contract
//   d_in[0] = y_true  (float32, B*N*N)
//   d_in[1] = y_pred  (float32, B*N*N)
//   d_in[2] = rows    (int64 or int32, K)
//   d_in[3] = cols    (int64 or int32, K)
//   d_out   = float32 scalar
// ---------------------------------------------------------------------------
extern "C" void kernel_launch(void* const* d_in, const int* in_sizes, int n_in,
                              void* d_out, int out_size)
{
    const float*        y_true = (const float*)d_in[0];
    const float*        y_pred = (const float*)d_in[1];
    const unsigned int* rows_w = (const unsigned int*)d_in[2];
    const unsigned int* cols_w = (const unsigned int*)d_in[3];
    float*              out    = (float*)d_out;

    masked_loss_fused_kernel<<<MB_B, 128>>>(y_true, y_pred, rows_w, cols_w, out);
}

// round 13
// speedup vs baseline: 1.3478x; 1.0048x over previous
#include <cuda_runtime.h>

// MaskedLoss: loss = sum_b sum_{unique (r,c)} (y_true[b,r,c] - y_pred[b,r,c])^2
// B=64, N=1000, K=128. Sparse gather (~8K of 64M positions).
// 32 blocks x 256 threads: ONE pair per thread, TWO batches per block
// (threads 0-127 -> batch 2b, 128-255 -> batch 2b+1). Halves the chip-wide
// same-address atomic burst (64 -> 32 arrivals) that serializes at L2.
// Critical path: [uint2 index load] -> warp-local width ballot -> [gather]
// -> F2I + redux.sync.add.s32 -> packed smem atomic (8 warps) -> packed
// global atomic (32 chip-wide). Dedup hash CAS (512-entry, keyed per half)
// hidden under gather latency. Ticket == data: the 32nd global arrival's
// pre-value IS the total — no fences, no second round trip.

#define MB_B     64
#define MB_N     1000
#define MB_GRID  32
#define MB_SCALE 4194304.0f          // 2^22
#define MB_INV   (1.0f / 4194304.0f)

// Packed global accumulator: bits [56,64) = block-arrival count, bits [0,56)
// = fixed-point sum (scale 2^22; total < 2^37, no carry into count).
// Zero at module load; last arrival resets it -> identical state per replay.
__device__ unsigned long long g_pack;

// Single-instruction integer warp sum (f32 redux doesn't exist on sm_103).
__device__ __forceinline__ int warp_sum_s32(int v) {
    int r;
    asm volatile("redux.sync.add.s32 %0, %1, 0xffffffff;" : "=r"(r) : "r"(v));
    return r;
}

__global__ __launch_bounds__(256)
void masked_loss_fused_kernel(const float* __restrict__ y_true,
                              const float* __restrict__ y_pred,
                              const unsigned int* __restrict__ rows_w,
                              const unsigned int* __restrict__ cols_w,
                              float* __restrict__ out)
{
    const int t    = threadIdx.x;        // 0..255
    const int half = t >> 7;             // 0/1 : which batch of this block
    const int k    = t & 127;            // 0..127 : index-pair id
    const int b    = 2 * blockIdx.x + half;   // batch row 0..63

    __shared__ int                s_tab[512];  // dedup table, 256 per half
    __shared__ unsigned long long s_pack;      // block packed [cnt:8|sum:56]

    s_tab[t]       = -1;
    s_tab[t + 256] = -1;
    if (t == 0) s_pack = 0ULL;

    // ---- epoch 1 (T0): every thread loads uint2 at (k & 63) — the first
    // 512B of each index array (pairs of warps re-read the same lines,
    // coalesced broadcast). int64: the pair IS element (k&63) (lo=x, hi=y).
    // int32: pair = indices 2(k&63), 2(k&63)+1.
    const int p = k & 63;
    uint2 r2 = __ldg((const uint2*)rows_w + p);
    uint2 c2 = __ldg((const uint2*)cols_w + p);

    // Non-faulting L2 prefetch of bytes [512,1024) (int64 upper half),
    // concurrent with epoch 1. Safe for either width.
    if (t >= 64 && t < 68) {
        asm volatile("prefetch.global.L2 [%0];"
                     :: "l"((const char*)rows_w + 512 + (t - 64) * 128));
    } else if (t >= 96 && t < 100) {
        asm volatile("prefetch.global.L2 [%0];"
                     :: "l"((const char*)cols_w + 512 + (t - 96) * 128));
    }

    // Barrier covers only the s_tab/s_pack stores above — it does NOT wait
    // on any load result (the width verdict below is warp-local).
    __syncthreads();

    // ---- width verdict, per-warp (no shared flag). Every warp sampled 32
    // hi-words from the first 512B. int64 (values<1000): all zero. int32:
    // 32 random indices in [0,1000); all-zero probability ~1e-96.
    const bool is_i32 = (__ballot_sync(0xffffffffu, r2.y != 0u) != 0u);

    int r, c;
    if (is_i32) {
        // k<64 -> even index 2p (.x); k>=64 -> odd index 2p+1 (.y);
        // across k=0..127 this covers every index exactly once.
        r = (k < 64) ? (int)r2.x : (int)r2.y;
        c = (k < 64) ? (int)c2.x : (int)c2.y;
    } else {
        // element k; threads k>=64 reload from bytes [512,1024) — in-bounds
        // for int64 (buffer is 1024B) and L2-prefetched above (~L2 hit).
        if (k >= 64) {
            r2 = __ldg((const uint2*)rows_w + k);
            c2 = __ldg((const uint2*)cols_w + k);
        }
        r = (int)r2.x;
        c = (int)c2.x;
    }
    const int my = r * MB_N + c;

    // ---- epoch 2: issue gathers immediately (independent of dedup; duplicate
    // threads hit the same address — L2 dedups). Offset < 2^31.
    const int off = b * (MB_N * MB_N) + my;
    const float yt = __ldg(y_true + off);
    const float yp = __ldg(y_pred + off);

    // ---- dedup via shared-mem hash, hidden under gather latency.
    // Keyed per half: each batch needs its own uniqueness winners.
    // Any single winner per (half, value) is correct.
    const int base = half << 8;                               // 0 or 256
    unsigned int h = ((unsigned int)my * 2654435761u) >> 24;  // 0..255
    bool uniq = false;
    for (;;) {
        int prev = atomicCAS(&s_tab[base + h], -1, my);
        if (prev == -1) { uniq = true; break; }
        if (prev == my) break;
        h = (h + 1) & 255;
    }

    const float d = yt - yp;
    // Fixed-point (2^22) BEFORE the reduce so the warp sum is one REDUX.S32.
    // Per-thread d^2 <~ 50 -> <2^30; warp sum fits s32 comfortably.
    const int vq = uniq ? __float2int_rn(d * d * MB_SCALE) : 0;

    // ---- warp reduce: one REDUX instead of 5 dependent SHFLs ---------------
    const int wsum = warp_sum_s32(vq);

    // ---- hierarchical packed-ticket tail -----------------------------------
    if ((t & 31) == 0) {
        // level 1: 8 warp leaders -> one smem u64 atomic; the pre-value count
        // tells the 8th arrival it holds the block total (no barrier).
        const unsigned long long contrib =
            (1ULL << 56) | (unsigned long long)(long long)wsum;
        const unsigned long long pre_s = atomicAdd(&s_pack, contrib);

        if ((pre_s >> 56) == 7ULL) {   // 8th warp of this block
            const unsigned long long blk =
                (pre_s + contrib) & 0x00FFFFFFFFFFFFFFULL;  // block fixed sum

            // level 2: one global u64 atomic per block (32 chip-wide).
            const unsigned long long gcontrib = (1ULL << 56) | blk;
            const unsigned long long pre_g = atomicAdd(&g_pack, gcontrib);

            if ((pre_g >> 56) == (unsigned long long)(MB_GRID - 1)) {
                // 32nd block: pre_g already carries the other 31 sums.
                const long long fixed =
                    (long long)((pre_g + gcontrib) & 0x00FFFFFFFFFFFFFFULL);
                // s64 -> f32 rounds once; * 2^-22 is exact (power of two).
                out[0] = (float)fixed * MB_INV;
                g_pack = 0ULL;   // reset for the next graph replay (sole
                                 // writer; stream order publishes it)
            }
        }
    }
}

// ---------------------------------------------------------------------------
// Launch contract
//   d_in[0] = y_true  (float32, B*N*N)
//   d_in[1] = y_pred  (float32, B*N*N)
//   d_in[2] = rows    (int64 or int32, K)
//   d_in[3] = cols    (int64 or int32, K)
//   d_out   = float32 scalar
// ---------------------------------------------------------------------------
extern "C" void kernel_launch(void* const* d_in, const int* in_sizes, int n_in,
                              void* d_out, int out_size)
{
    const float*        y_true = (const float*)d_in[0];
    const float*        y_pred = (const float*)d_in[1];
    const unsigned int* rows_w = (const unsigned int*)d_in[2];
    const unsigned int* cols_w = (const unsigned int*)d_in[3];
    float*              out    = (float*)d_out;

    masked_loss_fused_kernel<<<MB_GRID, 256>>>(y_true, y_pred, rows_w, cols_w, out);
}